// round 14
// baseline (speedup 1.0000x reference)
#include <cuda_runtime.h>
#include <cuda_fp16.h>
#include <math.h>

#define Bb 64
#define Nn 1024
#define DEG 8
#define ALPHA 0.2f

// Scratch (static __device__ globals — allocation-free per harness rules)
__device__ float g_s1[Bb * Nn];                         // h @ a1 (fp32)
__device__ float g_s2[Bb * Nn];                         // h @ a2 (fp32)
__device__ __align__(16) float   g_w[Bb * Nn * DEG];    // normalized softmax weights
__device__ __align__(16) __half2 g_h2[Bb * Nn * 32];    // 8 MB: h in fp16 (gather operand)

#define SAT_PITCH 132   // floats per k-row (128 rows + pad4, 16B-aligned)

__device__ __forceinline__ unsigned h2u(__half2 v) {
    return *reinterpret_cast<unsigned*>(&v);
}

// ---------------------------------------------------------------------------
// Kernel 1: h = atoms @ W, scalar FFMA, 4x8 per thread, 128-row CTA tile.
// Grid 512, ~50KB smem -> 4 CTAs/SM resident: finer wave granularity than the
// 256-row/grid-256 variant (which lost ~4.3us to 2-CTA quantization).
// Inner loop: 3 LDS.128 -> 32 FFMA per k. Epilogue: fp16 h store + fused
// s1/s2 (butterfly over the 8 cg lanes).
// ---------------------------------------------------------------------------
__global__ __launch_bounds__(256) void gat_gemm(const float* __restrict__ atoms,
                                                const float* __restrict__ W,
                                                const float* __restrict__ a)
{
    extern __shared__ __align__(16) float sm[];
    float* sAT = sm;                       // [64 k][SAT_PITCH] (row-transposed atoms)
    float* sW  = sm + 64 * SAT_PITCH;      // [64 k][64 c]

    const int tid  = threadIdx.x;
    const int row0 = blockIdx.x * 128;

    #pragma unroll
    for (int i = tid; i < 4096; i += 256) sW[i] = W[i];

    #pragma unroll
    for (int i = tid; i < 8192; i += 256) {
        int r = i >> 6, k = i & 63;
        sAT[k * SAT_PITCH + r] = atoms[(size_t)(row0 + r) * 64 + k];
    }
    __syncthreads();

    const int cg = tid & 7;    // col group: cols 8*cg..+7
    const int rg = tid >> 3;   // row group: rows 4*rg..+3

    float acc[4][8];
    #pragma unroll
    for (int r = 0; r < 4; r++)
        #pragma unroll
        for (int c = 0; c < 8; c++) acc[r][c] = 0.f;

    #pragma unroll 4
    for (int k = 0; k < 64; k++) {
        const float* Ak = &sAT[k * SAT_PITCH + rg * 4];
        const float* Wk = &sW[k * 64 + cg * 8];
        float4 av = *(const float4*)(Ak);
        float4 w0 = *(const float4*)(Wk);
        float4 w1 = *(const float4*)(Wk + 4);
        float ar[4] = {av.x, av.y, av.z, av.w};
        float wr[8] = {w0.x, w0.y, w0.z, w0.w, w1.x, w1.y, w1.z, w1.w};
        #pragma unroll
        for (int r = 0; r < 4; r++)
            #pragma unroll
            for (int c = 0; c < 8; c++)
                acc[r][c] = fmaf(ar[r], wr[c], acc[r][c]);
    }

    float a1v[8], a2v[8];
    #pragma unroll
    for (int c = 0; c < 8; c++) {
        a1v[c] = a[cg * 8 + c];
        a2v[c] = a[64 + cg * 8 + c];
    }

    #pragma unroll
    for (int r = 0; r < 4; r++) {
        const int row = row0 + rg * 4 + r;

        uint4 pk;
        pk.x = h2u(__floats2half2_rn(acc[r][0], acc[r][1]));
        pk.y = h2u(__floats2half2_rn(acc[r][2], acc[r][3]));
        pk.z = h2u(__floats2half2_rn(acc[r][4], acc[r][5]));
        pk.w = h2u(__floats2half2_rn(acc[r][6], acc[r][7]));
        *reinterpret_cast<uint4*>(&g_h2[(size_t)row * 32 + cg * 4]) = pk;

        float p1 = 0.f, p2 = 0.f;
        #pragma unroll
        for (int c = 0; c < 8; c++) {
            p1 = fmaf(acc[r][c], a1v[c], p1);
            p2 = fmaf(acc[r][c], a2v[c], p2);
        }
        #pragma unroll
        for (int off = 4; off > 0; off >>= 1) {
            p1 += __shfl_xor_sync(0xffffffffu, p1, off);
            p2 += __shfl_xor_sync(0xffffffffu, p2, off);
        }
        if (cg == 0) {
            g_s1[row] = p1;
            g_s2[row] = p2;
        }
    }
}

// ---------------------------------------------------------------------------
// Kernel 2: per-row softmax weights (one thread per row). Dedup + leaky-relu
// + softmax over <=8 unique neighbors (mask -9e15 underflows to exact 0).
// ---------------------------------------------------------------------------
__global__ __launch_bounds__(256) void gat_weights(const int* __restrict__ edges)
{
    const int g = blockIdx.x * 256 + threadIdx.x;
    const int b = g >> 10;
    const float* s2b = g_s2 + (b << 10);

    const int4 ea = __ldg(&((const int4*)edges)[2 * g]);
    const int4 eb = __ldg(&((const int4*)edges)[2 * g + 1]);
    int e[DEG] = { ea.x & (Nn - 1), ea.y & (Nn - 1), ea.z & (Nn - 1), ea.w & (Nn - 1),
                   eb.x & (Nn - 1), eb.y & (Nn - 1), eb.z & (Nn - 1), eb.w & (Nn - 1) };

    const float s1g = g_s1[g];

    float w[DEG];
    float mx = -1e30f;
    #pragma unroll
    for (int m = 0; m < DEG; m++) {
        float ev = s1g + __ldg(&s2b[e[m]]);
        ev = ev > 0.f ? ev : ALPHA * ev;
        bool dup = false;
        #pragma unroll
        for (int n = 0; n < m; n++) dup = dup || (e[n] == e[m]);
        w[m] = dup ? -1e30f : ev;
        mx = fmaxf(mx, w[m]);
    }
    float den = 0.f;
    #pragma unroll
    for (int m = 0; m < DEG; m++) {
        w[m] = (w[m] == -1e30f) ? 0.f : __expf(w[m] - mx);
        den += w[m];
    }
    const float inv = 1.f / den;

    ((float4*)g_w)[2 * g]     = make_float4(w[0] * inv, w[1] * inv, w[2] * inv, w[3] * inv);
    ((float4*)g_w)[2 * g + 1] = make_float4(w[4] * inv, w[5] * inv, w[6] * inv, w[7] * inv);
}

// ---------------------------------------------------------------------------
// Kernel 3: aggregation, FOUR rows per warp (32 independent gathers in
// flight; agg is gather-latency-bound and scaled 13.3->11us going 8->16, so
// 32 should take another bite). Edges/weights via uniform vector loads.
// ---------------------------------------------------------------------------
__global__ __launch_bounds__(256) void gat_agg(const int* __restrict__ edges,
                                               float* __restrict__ out)
{
    const int wid  = (blockIdx.x * 256 + threadIdx.x) >> 5;   // 0..16383
    const int lane = threadIdx.x & 31;
    const int g0   = wid * 4;                                  // 4 rows, same batch
    const int b    = g0 >> 10;

    const __half2* hb = g_h2 + ((size_t)b << 15);

    int4   ea[4], eb[4];
    float4 wa[4], wb[4];
    #pragma unroll
    for (int r = 0; r < 4; r++) {
        ea[r] = __ldg(&((const int4*)edges)[2 * (g0 + r)]);
        eb[r] = __ldg(&((const int4*)edges)[2 * (g0 + r) + 1]);
        wa[r] = __ldg(&((const float4*)g_w)[2 * (g0 + r)]);
        wb[r] = __ldg(&((const float4*)g_w)[2 * (g0 + r) + 1]);
    }

    float2 acc[4];
    #pragma unroll
    for (int r = 0; r < 4; r++) acc[r] = make_float2(0.f, 0.f);

    #define GSTEP(ACC, E, Wv) { \
        const float2 hv = __half22float2(__ldg(&hb[(size_t)((E) & (Nn - 1)) * 32 + lane])); \
        ACC.x = fmaf((Wv), hv.x, ACC.x); \
        ACC.y = fmaf((Wv), hv.y, ACC.y); }
    #pragma unroll
    for (int r = 0; r < 4; r++) {
        GSTEP(acc[r], ea[r].x, wa[r].x)
        GSTEP(acc[r], ea[r].y, wa[r].y)
        GSTEP(acc[r], ea[r].z, wa[r].z)
        GSTEP(acc[r], ea[r].w, wa[r].w)
        GSTEP(acc[r], eb[r].x, wb[r].x)
        GSTEP(acc[r], eb[r].y, wb[r].y)
        GSTEP(acc[r], eb[r].z, wb[r].z)
        GSTEP(acc[r], eb[r].w, wb[r].w)
    }
    #undef GSTEP

    #pragma unroll
    for (int r = 0; r < 4; r++) {
        float2 o;
        o.x = acc[r].x > 0.f ? acc[r].x : (__expf(acc[r].x) - 1.f);
        o.y = acc[r].y > 0.f ? acc[r].y : (__expf(acc[r].y) - 1.f);
        ((float2*)out)[(size_t)(g0 + r) * 32 + lane] = o;
    }
}

// ---------------------------------------------------------------------------
extern "C" void kernel_launch(void* const* d_in, const int* in_sizes, int n_in,
                              void* d_out, int out_size) {
    // Bind inputs BY ELEMENT COUNT (all four sizes distinct) — order-proof.
    const float* atoms = nullptr;   // 64*1024*64 = 4194304 (f32)
    const int*   edges = nullptr;   // 64*1024*8  = 524288  (i32: jax x64 off)
    const float* W     = nullptr;   // 64*64      = 4096    (f32)
    const float* a     = nullptr;   // 2*64*1     = 128     (f32)

    for (int i = 0; i < n_in; i++) {
        switch (in_sizes[i]) {
            case 4194304: atoms = (const float*)d_in[i]; break;
            case 524288:  edges = (const int*)d_in[i];   break;
            case 4096:    W     = (const float*)d_in[i]; break;
            case 128:     a     = (const float*)d_in[i]; break;
            default: break;
        }
    }
    if (!atoms || !edges || !W || !a) return;

    float* out = (float*)d_out;

    const int smem = (64 * SAT_PITCH + 64 * 64) * sizeof(float);  // 50176 B
    cudaFuncSetAttribute(gat_gemm, cudaFuncAttributeMaxDynamicSharedMemorySize, smem);

    gat_gemm<<<(Bb * Nn) / 128, 256, smem>>>(atoms, W, a);
    gat_weights<<<(Bb * Nn) / 256, 256>>>(edges);
    gat_agg<<<(Bb * Nn) / 4 / 8, 256>>>(edges, out);
}

// round 15
// speedup vs baseline: 1.1730x; 1.1730x over previous
#include <cuda_runtime.h>
#include <cuda_fp16.h>
#include <math.h>

#define Bb 64
#define Nn 1024
#define DEG 8
#define ALPHA 0.2f

// Scratch (static __device__ globals — allocation-free per harness rules)
__device__ float g_s1[Bb * Nn];                         // h @ a1 (fp32)
__device__ float g_s2[Bb * Nn];                         // h @ a2 (fp32)
__device__ __align__(16) __half2 g_h2[Bb * Nn * 32];    // 8 MB: h in fp16 (gather operand)

#define SAT_PITCH 260   // floats; 16B-aligned rows, spreads banks

__device__ __forceinline__ unsigned h2u(__half2 v) {
    return *reinterpret_cast<unsigned*>(&v);
}

// ---------------------------------------------------------------------------
// Kernel 1 (R6/R13, measured 20.0us twice): h = atoms @ W, scalar FFMA,
// 8x8 per thread (16 FMA per LDS.128 -> FFMA-bound). 256 rows per CTA.
// Epilogue: fp16 h store (coalesced uint4) + fused s1/s2.
// ---------------------------------------------------------------------------
__global__ __launch_bounds__(256) void gat_gemm(const float* __restrict__ atoms,
                                                const float* __restrict__ W,
                                                const float* __restrict__ a)
{
    extern __shared__ __align__(16) float sm[];
    float* sAT = sm;                       // [64 k][SAT_PITCH] (row-transposed atoms)
    float* sW  = sm + 64 * SAT_PITCH;      // [64 k][64 c]

    const int tid  = threadIdx.x;
    const int row0 = blockIdx.x * 256;

    #pragma unroll
    for (int i = tid; i < 4096; i += 256) sW[i] = W[i];

    #pragma unroll
    for (int i = tid; i < 16384; i += 256) {
        int r = i >> 6, k = i & 63;
        sAT[k * SAT_PITCH + r] = atoms[(size_t)(row0 + r) * 64 + k];
    }
    __syncthreads();

    const int cg = tid & 7;    // col group: cols 8*cg..+7
    const int rg = tid >> 3;   // row group: rows 8*rg..+7

    float acc[8][8];
    #pragma unroll
    for (int r = 0; r < 8; r++)
        #pragma unroll
        for (int c = 0; c < 8; c++) acc[r][c] = 0.f;

    #pragma unroll 4
    for (int k = 0; k < 64; k++) {
        const float* Ak = &sAT[k * SAT_PITCH + rg * 8];
        const float* Wk = &sW[k * 64 + cg * 8];
        float4 a0 = *(const float4*)(Ak);
        float4 a1 = *(const float4*)(Ak + 4);
        float4 w0 = *(const float4*)(Wk);
        float4 w1 = *(const float4*)(Wk + 4);
        float ar[8] = {a0.x, a0.y, a0.z, a0.w, a1.x, a1.y, a1.z, a1.w};
        float wr[8] = {w0.x, w0.y, w0.z, w0.w, w1.x, w1.y, w1.z, w1.w};
        #pragma unroll
        for (int r = 0; r < 8; r++)
            #pragma unroll
            for (int c = 0; c < 8; c++)
                acc[r][c] = fmaf(ar[r], wr[c], acc[r][c]);
    }

    float a1v[8], a2v[8];
    #pragma unroll
    for (int c = 0; c < 8; c++) {
        a1v[c] = a[cg * 8 + c];
        a2v[c] = a[64 + cg * 8 + c];
    }

    #pragma unroll
    for (int r = 0; r < 8; r++) {
        const int row = row0 + rg * 8 + r;

        uint4 pk;
        pk.x = h2u(__floats2half2_rn(acc[r][0], acc[r][1]));
        pk.y = h2u(__floats2half2_rn(acc[r][2], acc[r][3]));
        pk.z = h2u(__floats2half2_rn(acc[r][4], acc[r][5]));
        pk.w = h2u(__floats2half2_rn(acc[r][6], acc[r][7]));
        *reinterpret_cast<uint4*>(&g_h2[(size_t)row * 32 + cg * 4]) = pk;

        float p1 = 0.f, p2 = 0.f;
        #pragma unroll
        for (int c = 0; c < 8; c++) {
            p1 = fmaf(acc[r][c], a1v[c], p1);
            p2 = fmaf(acc[r][c], a2v[c], p2);
        }
        #pragma unroll
        for (int off = 4; off > 0; off >>= 1) {
            p1 += __shfl_xor_sync(0xffffffffu, p1, off);
            p2 += __shfl_xor_sync(0xffffffffu, p2, off);
        }
        if (cg == 0) {
            g_s1[row] = p1;
            g_s2[row] = p2;
        }
    }
}

// ---------------------------------------------------------------------------
// Kernel 2 (fused weights+agg): warp handles 2 rows.
// Phase A (lanes 0-15): lane = one neighbor slot of one row. Dedup via ONE
// __match_any_sync (key = edge | group<<12), leaky logits, softmax max/sum by
// 3-level xor-shfl inside each aligned 8-lane group.
// Phase B (all 32 lanes): shfl-broadcast the 8 (edge, weight) pairs per row,
// then the proven gather: lane owns feature pair {2*lane, 2*lane+1},
// 16 independent half2 gathers (L2-resident), fp32 FMA, ELU, float2 store.
// ---------------------------------------------------------------------------
__global__ __launch_bounds__(256) void gat_fused(const int* __restrict__ edges,
                                                 float* __restrict__ out)
{
    const int wid  = (blockIdx.x * 256 + threadIdx.x) >> 5;   // 0..32767
    const int lane = threadIdx.x & 31;
    const int g0   = wid * 2;                                  // rows g0, g0+1 (same batch)
    const int b    = g0 >> 10;

    // ---- Phase A: softmax weights for both rows on lanes 0-15 ----
    float wn = 0.f;
    int   e  = 0;
    if (lane < 16) {
        const int row = g0 + (lane >> 3);
        const int m   = lane & 7;
        e = __ldg(&edges[(size_t)row * DEG + m]) & (Nn - 1);
        const float s1g = g_s1[row];
        const float s2v = __ldg(&g_s2[(b << 10) | e]);
        float ev = s1g + s2v;
        ev = ev > 0.f ? ev : ALPHA * ev;

        const unsigned key = (unsigned)e | ((unsigned)(lane >> 3) << 12);
        const unsigned match = __match_any_sync(0x0000ffffu, key);
        const bool dup = (match & ((1u << lane) - 1u)) != 0u;

        float val = dup ? -1e30f : ev;
        float mx = val;
        #pragma unroll
        for (int off = 1; off <= 4; off <<= 1)
            mx = fmaxf(mx, __shfl_xor_sync(0x0000ffffu, mx, off));

        float w = dup ? 0.f : __expf(ev - mx);
        float den = w;
        #pragma unroll
        for (int off = 1; off <= 4; off <<= 1)
            den += __shfl_xor_sync(0x0000ffffu, den, off);

        wn = w / den;
    }

    // ---- broadcast (edge, weight) pairs to the full warp ----
    int   e0[DEG], e1[DEG];
    float w0[DEG], w1[DEG];
    #pragma unroll
    for (int m = 0; m < DEG; m++) {
        e0[m] = __shfl_sync(0xffffffffu, e,  m);
        w0[m] = __shfl_sync(0xffffffffu, wn, m);
        e1[m] = __shfl_sync(0xffffffffu, e,  8 + m);
        w1[m] = __shfl_sync(0xffffffffu, wn, 8 + m);
    }

    // ---- Phase B: gather-aggregate ----
    const __half2* hb = g_h2 + ((size_t)b << 15);

    float2 acc0 = make_float2(0.f, 0.f);
    float2 acc1 = make_float2(0.f, 0.f);
    #pragma unroll
    for (int m = 0; m < DEG; m++) {
        const float2 hv0 = __half22float2(__ldg(&hb[(size_t)e0[m] * 32 + lane]));
        const float2 hv1 = __half22float2(__ldg(&hb[(size_t)e1[m] * 32 + lane]));
        acc0.x = fmaf(w0[m], hv0.x, acc0.x);
        acc0.y = fmaf(w0[m], hv0.y, acc0.y);
        acc1.x = fmaf(w1[m], hv1.x, acc1.x);
        acc1.y = fmaf(w1[m], hv1.y, acc1.y);
    }

    float2 o0, o1;
    o0.x = acc0.x > 0.f ? acc0.x : (__expf(acc0.x) - 1.f);
    o0.y = acc0.y > 0.f ? acc0.y : (__expf(acc0.y) - 1.f);
    o1.x = acc1.x > 0.f ? acc1.x : (__expf(acc1.x) - 1.f);
    o1.y = acc1.y > 0.f ? acc1.y : (__expf(acc1.y) - 1.f);
    ((float2*)out)[(size_t)g0 * 32 + lane]       = o0;
    ((float2*)out)[(size_t)(g0 + 1) * 32 + lane] = o1;
}

// ---------------------------------------------------------------------------
extern "C" void kernel_launch(void* const* d_in, const int* in_sizes, int n_in,
                              void* d_out, int out_size) {
    // Bind inputs BY ELEMENT COUNT (all four sizes distinct) — order-proof.
    const float* atoms = nullptr;   // 64*1024*64 = 4194304 (f32)
    const int*   edges = nullptr;   // 64*1024*8  = 524288  (i32: jax x64 off)
    const float* W     = nullptr;   // 64*64      = 4096    (f32)
    const float* a     = nullptr;   // 2*64*1     = 128     (f32)

    for (int i = 0; i < n_in; i++) {
        switch (in_sizes[i]) {
            case 4194304: atoms = (const float*)d_in[i]; break;
            case 524288:  edges = (const int*)d_in[i];   break;
            case 4096:    W     = (const float*)d_in[i]; break;
            case 128:     a     = (const float*)d_in[i]; break;
            default: break;
        }
    }
    if (!atoms || !edges || !W || !a) return;

    float* out = (float*)d_out;

    const int smem = (64 * SAT_PITCH + 64 * 64) * sizeof(float);  // 82944 B
    cudaFuncSetAttribute(gat_gemm, cudaFuncAttributeMaxDynamicSharedMemorySize, smem);

    gat_gemm<<<(Bb * Nn) / 256, 256, smem>>>(atoms, W, a);
    gat_fused<<<(Bb * Nn) / 2 / 8, 256>>>(edges, out);
}